// round 5
// baseline (speedup 1.0000x reference)
#include <cuda_runtime.h>
#include <cuda_fp16.h>
#include <cstdint>

// Problem constants
#define B_    16
#define CIN   256
#define COUT  256
#define EPS_F 1e-8f
// Winograd F(2x2,3x3): 32x32 = 1024 tiles per (b); T = b*1024 + ty*32 + tx
#define NT    16384            // total tiles (16 b * 1024)

// ================= scratch =================
__device__ float g_snorm;
__device__ float g_wsq[COUT*CIN];
__device__ float g_invwn[COUT];
__device__ float g_scale[B_*COUT];
// V: [tap 16][T 16384][ci 256] fp16 (134MB)
__device__ __align__(16) __half g_V[(size_t)16*NT*CIN];
// U: [tap 16][co 256][ci 256] fp16 (2MB)
__device__ __align__(16) __half g_U[16*COUT*CIN];

// ================= helpers =================
__device__ __forceinline__ void mma_fp16(float& d0, float& d1, float& d2, float& d3,
                                         uint32_t a0, uint32_t a1, uint32_t a2, uint32_t a3,
                                         uint32_t b0, uint32_t b1) {
    asm volatile("mma.sync.aligned.m16n8k16.row.col.f32.f16.f16.f32 "
                 "{%0,%1,%2,%3}, {%4,%5,%6,%7}, {%8,%9}, {%0,%1,%2,%3};"
                 : "+f"(d0), "+f"(d1), "+f"(d2), "+f"(d3)
                 : "r"(a0), "r"(a1), "r"(a2), "r"(a3), "r"(b0), "r"(b1));
}
__device__ __forceinline__ void cp_async16(uint32_t saddr, const void* gaddr) {
    asm volatile("cp.async.cg.shared.global [%0], [%1], 16;"
                 :: "r"(saddr), "l"(gaddr) : "memory");
}
__device__ __forceinline__ void cp_commit() {
    asm volatile("cp.async.commit_group;" ::: "memory");
}
__device__ __forceinline__ void cp_wait0() {
    asm volatile("cp.async.wait_group 0;" ::: "memory");
}
__device__ __forceinline__ uint32_t smem_u32(const void* p) {
    uint32_t a;
    asm("{ .reg .u64 t; cvta.to.shared.u64 t, %1; cvt.u32.u64 %0, t; }"
        : "=r"(a) : "l"(p));
    return a;
}

// ================= norm/scale kernels (proven) =================
__global__ void k_snorm(const float* __restrict__ s) {
    __shared__ float red[256];
    float acc = 0.f;
    for (int i = threadIdx.x; i < B_*CIN; i += 256) { float v = s[i]; acc += v*v; }
    red[threadIdx.x] = acc; __syncthreads();
    for (int off = 128; off > 0; off >>= 1) {
        if (threadIdx.x < off) red[threadIdx.x] += red[threadIdx.x + off];
        __syncthreads();
    }
    if (threadIdx.x == 0) g_snorm = rsqrtf(red[0] / (float)(B_*CIN));
}
__global__ void k_wstats(const float* __restrict__ w) {
    __shared__ float red[256];
    int co = blockIdx.x, ci = threadIdx.x;
    const float* wp = w + ((size_t)co * CIN + ci) * 9;
    float s9 = 0.f;
#pragma unroll
    for (int k = 0; k < 9; k++) { float v = wp[k]; s9 += v*v; }
    g_wsq[co*CIN + ci] = s9;
    red[ci] = s9; __syncthreads();
    for (int off = 128; off > 0; off >>= 1) {
        if (ci < off) red[ci] += red[ci + off];
        __syncthreads();
    }
    if (ci == 0) g_invwn[co] = rsqrtf(red[0] / (float)(CIN*9));
}
__global__ void k_scale(const float* __restrict__ s) {
    __shared__ float red[256];
    int co = blockIdx.x, b = blockIdx.y, ci = threadIdx.x;
    float sn = s[b*CIN + ci] * g_snorm;
    red[ci] = sn*sn * g_wsq[co*CIN + ci]; __syncthreads();
    for (int off = 128; off > 0; off >>= 1) {
        if (ci < off) red[ci] += red[ci + off];
        __syncthreads();
    }
    if (ci == 0) {
        float iw = g_invwn[co];
        g_scale[b*COUT + co] = iw * rsqrtf(iw*iw*red[0] + EPS_F);
    }
}

// ================= weight transform: U = G g G^T =================
// grid 256 (co), 256 threads (ci)
__global__ void k_wino_w(const float* __restrict__ w) {
    int co = blockIdx.x, ci = threadIdx.x;
    const float* gp = w + ((size_t)co*CIN + ci)*9;
    float g0[3], g1[3], g2[3];
#pragma unroll
    for (int c = 0; c < 3; ++c) { g0[c]=gp[c]; g1[c]=gp[3+c]; g2[c]=gp[6+c]; }
    float tm[4][3];
#pragma unroll
    for (int c = 0; c < 3; ++c) {
        tm[0][c] = g0[c];
        tm[1][c] = 0.5f*(g0[c] + g1[c] + g2[c]);
        tm[2][c] = 0.5f*(g0[c] - g1[c] + g2[c]);
        tm[3][c] = g2[c];
    }
#pragma unroll
    for (int r = 0; r < 4; ++r) {
        float u0 = tm[r][0];
        float u1 = 0.5f*(tm[r][0] + tm[r][1] + tm[r][2]);
        float u2 = 0.5f*(tm[r][0] - tm[r][1] + tm[r][2]);
        float u3 = tm[r][2];
        g_U[(((size_t)((r*4+0)*COUT + co))<<8) + ci] = __float2half_rn(u0);
        g_U[(((size_t)((r*4+1)*COUT + co))<<8) + ci] = __float2half_rn(u1);
        g_U[(((size_t)((r*4+2)*COUT + co))<<8) + ci] = __float2half_rn(u2);
        g_U[(((size_t)((r*4+3)*COUT + co))<<8) + ci] = __float2half_rn(u3);
    }
}

// ================= input transform: V = B^T (x*s*snorm) B =================
// grid (32 ty, 8 ciT, 16 b), 256 threads (= 32 ci x 8 txq, ci = lane)
__global__ void k_wino_x(const float* __restrict__ x, const float* __restrict__ s) {
    __shared__ float sm[4][32][67];   // [row][ci][col -1..64 -> idx 0..65]
    const int tid = threadIdx.x;
    const int ty = blockIdx.x, ciT = blockIdx.y, b = blockIdx.z;
    const float snorm = g_snorm;
    const int r0 = 2*ty - 1;
    // load 32ci x 4 rows x 64 cols (modulated), zero-pad OOB + halo cols
#pragma unroll
    for (int k = 0; k < 8; ++k) {
        int lin = k*256 + tid;            // (ci 32)(r 4)(c4 16)
        int c4 = lin & 15, r = (lin >> 4) & 3, ci = lin >> 6;
        int gci = ciT*32 + ci;
        int gr = r0 + r;
        float4 v = make_float4(0.f, 0.f, 0.f, 0.f);
        if ((unsigned)gr < 64u)
            v = *(const float4*)(x + (((size_t)(b*CIN + gci)) << 12) + gr*64 + c4*4);
        float m = s[b*CIN + gci] * snorm;
        float* d = &sm[r][ci][1 + 4*c4];
        d[0] = v.x*m; d[1] = v.y*m; d[2] = v.z*m; d[3] = v.w*m;
        if (c4 == 0)  sm[r][ci][0]  = 0.f;
        if (c4 == 15) sm[r][ci][65] = 0.f;
    }
    __syncthreads();
    const int ci = tid & 31, txq = tid >> 5;
#pragma unroll
    for (int k = 0; k < 4; ++k) {
        int tx = txq + 8*k;
        float d[4][4];
#pragma unroll
        for (int r = 0; r < 4; ++r)
#pragma unroll
            for (int c = 0; c < 4; ++c) d[r][c] = sm[r][ci][2*tx + c];
        // rows: m = B^T d
        float m0[4], m1[4], m2[4], m3[4];
#pragma unroll
        for (int j = 0; j < 4; ++j) {
            m0[j] = d[0][j] - d[2][j];
            m1[j] = d[1][j] + d[2][j];
            m2[j] = d[2][j] - d[1][j];
            m3[j] = d[1][j] - d[3][j];
        }
        float V[4][4];
#pragma unroll
        for (int r = 0; r < 4; ++r) {
            const float* mr = (r==0)?m0:(r==1)?m1:(r==2)?m2:m3;
            V[r][0] = mr[0] - mr[2];
            V[r][1] = mr[1] + mr[2];
            V[r][2] = mr[2] - mr[1];
            V[r][3] = mr[1] - mr[3];
        }
        int T = b*1024 + ty*32 + tx;
#pragma unroll
        for (int r = 0; r < 4; ++r)
#pragma unroll
            for (int c = 0; c < 4; ++c)
                g_V[(((size_t)((r*4+c)*NT + T)) << 8) + ciT*32 + ci] =
                    __float2half_rn(V[r][c]);
    }
}

// ================= Winograd GEMM + fused inverse transform =================
// CTA: 64 co x 128 T. 8 warps: wm = wid&3 (m16), wn = wid>>2 (n64).
// Loop 16 taps x 4 ci-chunks(64); M accum per tap, folded into Y (4 px) regs.
// smem: A[2][64][72], B[2][128][72] halfs, cp.async double-buffered.
#define ASTR 72
#define A_HALFS (64*ASTR)
#define B_HALFS (128*ASTR)
#define SMEM_BYTES ((2*A_HALFS + 2*B_HALFS)*2)   // 55296

__global__ __launch_bounds__(256, 1)
void k_conv(float* __restrict__ out) {
    extern __shared__ __half smem[];
    __half* sA = smem;                    // [2][64][72]
    __half* sB = smem + 2*A_HALFS;        // [2][128][72]
    const uint32_t sA_u = smem_u32(sA);
    const uint32_t sB_u = smem_u32(sB);

    const int t    = threadIdx.x;
    const int lane = t & 31;
    const int wm   = (t >> 5) & 3;        // co block (m16)
    const int wn   = t >> 7;              // T block (n64)
    const int g    = lane >> 2;
    const int t4   = lane & 3;

    const int coT   = blockIdx.x;         // 0..3
    const int Tbase = blockIdx.y * 128;   // 0..16256
    const int b     = Tbase >> 10;

    float Y[4][8][4];
#pragma unroll
    for (int px = 0; px < 4; ++px)
#pragma unroll
        for (int nb = 0; nb < 8; ++nb)
#pragma unroll
            for (int q = 0; q < 4; ++q) Y[px][nb][q] = 0.f;

    // ---- phase loader (tap = p>>2, kc = p&3) ----
    auto load_phase = [&](int p, int j) {
        int tap = p >> 2, kc = p & 3;
        // A: 512 uint4, 2/thread
#pragma unroll
        for (int k2 = 0; k2 < 2; ++k2) {
            int lin = k2*256 + t;
            int row = lin >> 3, q = lin & 7;
            const __half* src = g_U + (((size_t)(tap*COUT + coT*64 + row)) << 8)
                              + kc*64 + q*8;
            cp_async16(sA_u + (j*A_HALFS + row*ASTR + q*8)*2, src);
        }
        // B: 1024 uint4, 4/thread
#pragma unroll
        for (int k4 = 0; k4 < 4; ++k4) {
            int lin = k4*256 + t;
            int row = lin >> 3, q = lin & 7;
            const __half* src = g_V + (((size_t)(tap*NT + Tbase + row)) << 8)
                              + kc*64 + q*8;
            cp_async16(sB_u + (j*B_HALFS + row*ASTR + q*8)*2, src);
        }
    };

    load_phase(0, 0);
    cp_commit();
    cp_wait0();
    __syncthreads();

    float M[8][4];
    const int AT0[4] = {1, 1, 1, 0};
    const int AT1[4] = {0, 1, -1, -1};

    for (int p = 0; p < 64; ++p) {
        const int j = p & 1;
        if (p < 63) { load_phase(p + 1, j ^ 1); cp_commit(); }

        if ((p & 3) == 0) {
#pragma unroll
            for (int nb = 0; nb < 8; ++nb)
#pragma unroll
                for (int q = 0; q < 4; ++q) M[nb][q] = 0.f;
        }

        const __half* A = sA + j*A_HALFS;
        const __half* Bm = sB + j*B_HALFS;
#pragma unroll
        for (int ks = 0; ks < 4; ++ks) {
            const __half* ap = A + (wm*16 + g)*ASTR + ks*16 + 2*t4;
            uint32_t a0 = *(const uint32_t*)(ap);
            uint32_t a1 = *(const uint32_t*)(ap + 8*ASTR);
            uint32_t a2 = *(const uint32_t*)(ap + 8);
            uint32_t a3 = *(const uint32_t*)(ap + 8*ASTR + 8);
            uint32_t bf[8][2];
#pragma unroll
            for (int nb = 0; nb < 8; ++nb) {
                const __half* bp = Bm + (wn*64 + nb*8 + g)*ASTR + ks*16 + 2*t4;
                bf[nb][0] = *(const uint32_t*)(bp);
                bf[nb][1] = *(const uint32_t*)(bp + 8);
            }
#pragma unroll
            for (int nb = 0; nb < 8; ++nb)
                mma_fp16(M[nb][0], M[nb][1], M[nb][2], M[nb][3],
                         a0, a1, a2, a3, bf[nb][0], bf[nb][1]);
        }

        if ((p & 3) == 3) {
            int tap = p >> 2;
            int r = tap >> 2, c = tap & 3;
#pragma unroll
            for (int i = 0; i < 2; ++i) {
                int ar = (i == 0) ? AT0[r] : AT1[r];
                if (ar == 0) continue;
#pragma unroll
                for (int jj = 0; jj < 2; ++jj) {
                    int ac = (jj == 0) ? AT0[c] : AT1[c];
                    if (ac == 0) continue;
                    float cf = (float)(ar * ac);
#pragma unroll
                    for (int nb = 0; nb < 8; ++nb)
#pragma unroll
                        for (int q = 0; q < 4; ++q)
                            Y[i*2 + jj][nb][q] += cf * M[nb][q];
                }
            }
        }

        cp_wait0();
        __syncthreads();
    }

    // ---- epilogue: demod scale + scatter 2x2 px per tile ----
#pragma unroll
    for (int co2 = 0; co2 < 2; ++co2) {
        int coG = coT*64 + wm*16 + g + co2*8;
        float sc = g_scale[b*COUT + coG];
        float* ob = out + (((size_t)(b*COUT + coG)) << 12);
#pragma unroll
        for (int nb = 0; nb < 8; ++nb) {
#pragma unroll
            for (int kT = 0; kT < 2; ++kT) {
                int q = co2*2 + kT;
                int T0 = Tbase + wn*64 + nb*8 + 2*t4 + kT;
                int rel = T0 & 1023;
                int tyy = rel >> 5, txx = rel & 31;
#pragma unroll
                for (int i = 0; i < 2; ++i) {
                    float2 v = make_float2(sc * Y[i*2 + 0][nb][q],
                                           sc * Y[i*2 + 1][nb][q]);
                    *(float2*)(ob + (2*tyy + i)*64 + 2*txx) = v;
                }
            }
        }
    }
}

// ================= launcher =================
extern "C" void kernel_launch(void* const* d_in, const int* in_sizes, int n_in,
                              void* d_out, int out_size) {
    const float* x = (const float*)d_in[0];   // [B, CIN, 64, 64]
    const float* s = (const float*)d_in[1];   // [B, CIN]
    const float* w = (const float*)d_in[2];   // [COUT, CIN, 3, 3]
    float* out = (float*)d_out;               // [B, COUT, 64, 64]

    cudaFuncSetAttribute(k_conv, cudaFuncAttributeMaxDynamicSharedMemorySize,
                         SMEM_BYTES);

    k_snorm<<<1, 256>>>(s);
    k_wstats<<<COUT, 256>>>(w);
    dim3 gs(COUT, B_);
    k_scale<<<gs, 256>>>(s);
    k_wino_w<<<COUT, 256>>>(w);
    dim3 gx(32, 8, B_);
    k_wino_x<<<gx, 256>>>(x, s);
    dim3 gc(4, 128);
    k_conv<<<gc, 256, SMEM_BYTES>>>(out);
}

// round 6
// speedup vs baseline: 1.0952x; 1.0952x over previous
#include <cuda_runtime.h>
#include <cuda_fp16.h>
#include <cstdint>

// Problem constants
#define B_    16
#define CIN   256
#define COUT  256
#define EPS_F 1e-8f
// Winograd F(2x2,3x3): 32x32 = 1024 tiles per (b); T = b*1024 + ty*32 + tx
#define NT    16384            // total tiles (16 b * 1024)

// ================= scratch =================
__device__ float g_snorm;
__device__ float g_wsq[COUT*CIN];
__device__ float g_invwn[COUT];
__device__ float g_scale[B_*COUT];
// V: [tap 16][T 16384][ci 256] fp16 (134MB)
__device__ __align__(16) __half g_V[(size_t)16*NT*CIN];
// U: [tap 16][co 256][ci 256] fp16 (2MB)
__device__ __align__(16) __half g_U[16*COUT*CIN];

// ================= helpers =================
__device__ __forceinline__ void mma_fp16(float& d0, float& d1, float& d2, float& d3,
                                         uint32_t a0, uint32_t a1, uint32_t a2, uint32_t a3,
                                         uint32_t b0, uint32_t b1) {
    asm volatile("mma.sync.aligned.m16n8k16.row.col.f32.f16.f16.f32 "
                 "{%0,%1,%2,%3}, {%4,%5,%6,%7}, {%8,%9}, {%0,%1,%2,%3};"
                 : "+f"(d0), "+f"(d1), "+f"(d2), "+f"(d3)
                 : "r"(a0), "r"(a1), "r"(a2), "r"(a3), "r"(b0), "r"(b1));
}
__device__ __forceinline__ void cp_async16(uint32_t saddr, const void* gaddr) {
    asm volatile("cp.async.cg.shared.global [%0], [%1], 16;"
                 :: "r"(saddr), "l"(gaddr) : "memory");
}
__device__ __forceinline__ void cp_commit() {
    asm volatile("cp.async.commit_group;" ::: "memory");
}
__device__ __forceinline__ void cp_wait2() {
    asm volatile("cp.async.wait_group 2;" ::: "memory");
}
__device__ __forceinline__ uint32_t smem_u32(const void* p) {
    uint32_t a;
    asm("{ .reg .u64 t; cvta.to.shared.u64 t, %1; cvt.u32.u64 %0, t; }"
        : "=r"(a) : "l"(p));
    return a;
}

// ================= norm/scale kernels (proven) =================
__global__ void k_snorm(const float* __restrict__ s) {
    __shared__ float red[256];
    float acc = 0.f;
    for (int i = threadIdx.x; i < B_*CIN; i += 256) { float v = s[i]; acc += v*v; }
    red[threadIdx.x] = acc; __syncthreads();
    for (int off = 128; off > 0; off >>= 1) {
        if (threadIdx.x < off) red[threadIdx.x] += red[threadIdx.x + off];
        __syncthreads();
    }
    if (threadIdx.x == 0) g_snorm = rsqrtf(red[0] / (float)(B_*CIN));
}
__global__ void k_wstats(const float* __restrict__ w) {
    __shared__ float red[256];
    int co = blockIdx.x, ci = threadIdx.x;
    const float* wp = w + ((size_t)co * CIN + ci) * 9;
    float s9 = 0.f;
#pragma unroll
    for (int k = 0; k < 9; k++) { float v = wp[k]; s9 += v*v; }
    g_wsq[co*CIN + ci] = s9;
    red[ci] = s9; __syncthreads();
    for (int off = 128; off > 0; off >>= 1) {
        if (ci < off) red[ci] += red[ci + off];
        __syncthreads();
    }
    if (ci == 0) g_invwn[co] = rsqrtf(red[0] / (float)(CIN*9));
}
__global__ void k_scale(const float* __restrict__ s) {
    __shared__ float red[256];
    int co = blockIdx.x, b = blockIdx.y, ci = threadIdx.x;
    float sn = s[b*CIN + ci] * g_snorm;
    red[ci] = sn*sn * g_wsq[co*CIN + ci]; __syncthreads();
    for (int off = 128; off > 0; off >>= 1) {
        if (ci < off) red[ci] += red[ci + off];
        __syncthreads();
    }
    if (ci == 0) {
        float iw = g_invwn[co];
        g_scale[b*COUT + co] = iw * rsqrtf(iw*iw*red[0] + EPS_F);
    }
}

// ================= weight transform: U = G g G^T =================
__global__ void k_wino_w(const float* __restrict__ w) {
    int co = blockIdx.x, ci = threadIdx.x;
    const float* gp = w + ((size_t)co*CIN + ci)*9;
    float g0[3], g1[3], g2[3];
#pragma unroll
    for (int c = 0; c < 3; ++c) { g0[c]=gp[c]; g1[c]=gp[3+c]; g2[c]=gp[6+c]; }
    float tm[4][3];
#pragma unroll
    for (int c = 0; c < 3; ++c) {
        tm[0][c] = g0[c];
        tm[1][c] = 0.5f*(g0[c] + g1[c] + g2[c]);
        tm[2][c] = 0.5f*(g0[c] - g1[c] + g2[c]);
        tm[3][c] = g2[c];
    }
#pragma unroll
    for (int r = 0; r < 4; ++r) {
        float u0 = tm[r][0];
        float u1 = 0.5f*(tm[r][0] + tm[r][1] + tm[r][2]);
        float u2 = 0.5f*(tm[r][0] - tm[r][1] + tm[r][2]);
        float u3 = tm[r][2];
        g_U[(((size_t)((r*4+0)*COUT + co))<<8) + ci] = __float2half_rn(u0);
        g_U[(((size_t)((r*4+1)*COUT + co))<<8) + ci] = __float2half_rn(u1);
        g_U[(((size_t)((r*4+2)*COUT + co))<<8) + ci] = __float2half_rn(u2);
        g_U[(((size_t)((r*4+3)*COUT + co))<<8) + ci] = __float2half_rn(u3);
    }
}

// ================= input transform: V = B^T (x*s*snorm) B =================
// grid (32 ty, 8 ciT, 16 b), 256 threads (= 32 ci x 8 txq, ci = lane)
__global__ void k_wino_x(const float* __restrict__ x, const float* __restrict__ s) {
    __shared__ float sm[4][32][67];   // [row][ci][col -1..64 -> idx 0..65]
    const int tid = threadIdx.x;
    const int ty = blockIdx.x, ciT = blockIdx.y, b = blockIdx.z;
    const float snorm = g_snorm;
    const int r0 = 2*ty - 1;
#pragma unroll
    for (int k = 0; k < 8; ++k) {
        int lin = k*256 + tid;            // (ci 32)(r 4)(c4 16)
        int c4 = lin & 15, r = (lin >> 4) & 3, ci = lin >> 6;
        int gci = ciT*32 + ci;
        int gr = r0 + r;
        float4 v = make_float4(0.f, 0.f, 0.f, 0.f);
        if ((unsigned)gr < 64u)
            v = *(const float4*)(x + (((size_t)(b*CIN + gci)) << 12) + gr*64 + c4*4);
        float m = s[b*CIN + gci] * snorm;
        float* d = &sm[r][ci][1 + 4*c4];
        d[0] = v.x*m; d[1] = v.y*m; d[2] = v.z*m; d[3] = v.w*m;
        if (c4 == 0)  sm[r][ci][0]  = 0.f;
        if (c4 == 15) sm[r][ci][65] = 0.f;
    }
    __syncthreads();
    const int ci = tid & 31, txq = tid >> 5;
#pragma unroll
    for (int k = 0; k < 4; ++k) {
        int tx = txq + 8*k;
        float d[4][4];
#pragma unroll
        for (int r = 0; r < 4; ++r)
#pragma unroll
            for (int c = 0; c < 4; ++c) d[r][c] = sm[r][ci][2*tx + c];
        float m0[4], m1[4], m2[4], m3[4];
#pragma unroll
        for (int j = 0; j < 4; ++j) {
            m0[j] = d[0][j] - d[2][j];
            m1[j] = d[1][j] + d[2][j];
            m2[j] = d[2][j] - d[1][j];
            m3[j] = d[1][j] - d[3][j];
        }
        float V[4][4];
#pragma unroll
        for (int r = 0; r < 4; ++r) {
            const float* mr = (r==0)?m0:(r==1)?m1:(r==2)?m2:m3;
            V[r][0] = mr[0] - mr[2];
            V[r][1] = mr[1] + mr[2];
            V[r][2] = mr[2] - mr[1];
            V[r][3] = mr[1] - mr[3];
        }
        int T = b*1024 + ty*32 + tx;
#pragma unroll
        for (int r = 0; r < 4; ++r)
#pragma unroll
            for (int c = 0; c < 4; ++c)
                g_V[(((size_t)((r*4+c)*NT + T)) << 8) + ciT*32 + ci] =
                    __float2half_rn(V[r][c]);
    }
}

// ================= Winograd GEMM + fused inverse transform =================
// CTA: 64 co x 128 T. 8 warps: wm = wid&3 (m16), wn = wid>>2 (n64).
// 64 phases = 16 taps x 4 ci-chunks(64). 4-stage cp.async pipeline,
// wait_group 2 BEFORE compute, single barrier per phase.
#define ASTR 72
#define A_HALFS (64*ASTR)
#define B_HALFS (128*ASTR)
#define STAGE_HALFS (A_HALFS + B_HALFS)          // 13824
#define NSTAGE 4
#define SMEM_BYTES (NSTAGE*STAGE_HALFS*2)        // 110592

__global__ __launch_bounds__(256, 1)
void k_conv(float* __restrict__ out) {
    extern __shared__ __half smem[];
    const uint32_t smem_base = smem_u32(smem);

    const int t    = threadIdx.x;
    const int lane = t & 31;
    const int wm   = (t >> 5) & 3;        // co block (m16)
    const int wn   = t >> 7;              // T block (n64)
    const int g    = lane >> 2;
    const int t4   = lane & 3;

    const int coT   = blockIdx.x;         // 0..3
    const int Tbase = blockIdx.y * 128;   // 0..16256
    const int b     = Tbase >> 10;

    float Y[4][8][4];
#pragma unroll
    for (int px = 0; px < 4; ++px)
#pragma unroll
        for (int nb = 0; nb < 8; ++nb)
#pragma unroll
            for (int q = 0; q < 4; ++q) Y[px][nb][q] = 0.f;

    // ---- phase loader (tap = p>>2, kc = p&3) into stage j ----
    auto load_phase = [&](int p, int j) {
        int tap = p >> 2, kc = p & 3;
        uint32_t sbase = smem_base + (j*STAGE_HALFS)*2;
        // A: 512 uint4, 2/thread
#pragma unroll
        for (int k2 = 0; k2 < 2; ++k2) {
            int lin = k2*256 + t;
            int row = lin >> 3, q = lin & 7;
            const __half* src = g_U + (((size_t)(tap*COUT + coT*64 + row)) << 8)
                              + kc*64 + q*8;
            cp_async16(sbase + (row*ASTR + q*8)*2, src);
        }
        // B: 1024 uint4, 4/thread
#pragma unroll
        for (int k4 = 0; k4 < 4; ++k4) {
            int lin = k4*256 + t;
            int row = lin >> 3, q = lin & 7;
            const __half* src = g_V + (((size_t)(tap*NT + Tbase + row)) << 8)
                              + kc*64 + q*8;
            cp_async16(sbase + (A_HALFS + row*ASTR + q*8)*2, src);
        }
    };

    // prologue: stages 0..2
#pragma unroll
    for (int p = 0; p < 3; ++p) { load_phase(p, p); cp_commit(); }

    float M[8][4];
    const int AT0[4] = {1, 1, 1, 0};
    const int AT1[4] = {0, 1, -1, -1};

    for (int p = 0; p < 64; ++p) {
        const int j = p & 3;
        cp_wait2();             // stage j (phase p) resident; p+1, p+2 in flight
        __syncthreads();        // all threads see stage j; slot (p-1)&3 reusable
        if (p + 3 < 64) load_phase(p + 3, (p + 3) & 3);
        cp_commit();            // commit (possibly empty) group: invariant count

        if ((p & 3) == 0) {
#pragma unroll
            for (int nb = 0; nb < 8; ++nb)
#pragma unroll
                for (int q = 0; q < 4; ++q) M[nb][q] = 0.f;
        }

        const __half* A  = smem + j*STAGE_HALFS;
        const __half* Bm = A + A_HALFS;
#pragma unroll
        for (int ks = 0; ks < 4; ++ks) {
            const __half* ap = A + (wm*16 + g)*ASTR + ks*16 + 2*t4;
            uint32_t a0 = *(const uint32_t*)(ap);
            uint32_t a1 = *(const uint32_t*)(ap + 8*ASTR);
            uint32_t a2 = *(const uint32_t*)(ap + 8);
            uint32_t a3 = *(const uint32_t*)(ap + 8*ASTR + 8);
            uint32_t bf[8][2];
#pragma unroll
            for (int nb = 0; nb < 8; ++nb) {
                const __half* bp = Bm + (wn*64 + nb*8 + g)*ASTR + ks*16 + 2*t4;
                bf[nb][0] = *(const uint32_t*)(bp);
                bf[nb][1] = *(const uint32_t*)(bp + 8);
            }
#pragma unroll
            for (int nb = 0; nb < 8; ++nb)
                mma_fp16(M[nb][0], M[nb][1], M[nb][2], M[nb][3],
                         a0, a1, a2, a3, bf[nb][0], bf[nb][1]);
        }

        if ((p & 3) == 3) {
            int tap = p >> 2;
            int r = tap >> 2, c = tap & 3;
#pragma unroll
            for (int i = 0; i < 2; ++i) {
                int ar = (i == 0) ? AT0[r] : AT1[r];
                if (ar == 0) continue;
#pragma unroll
                for (int jj = 0; jj < 2; ++jj) {
                    int ac = (jj == 0) ? AT0[c] : AT1[c];
                    if (ac == 0) continue;
                    float cf = (float)(ar * ac);
#pragma unroll
                    for (int nb = 0; nb < 8; ++nb)
#pragma unroll
                        for (int q = 0; q < 4; ++q)
                            Y[i*2 + jj][nb][q] += cf * M[nb][q];
                }
            }
        }
    }

    // ---- epilogue: demod scale + scatter 2x2 px per tile ----
#pragma unroll
    for (int co2 = 0; co2 < 2; ++co2) {
        int coG = coT*64 + wm*16 + g + co2*8;
        float sc = g_scale[b*COUT + coG];
        float* ob = out + (((size_t)(b*COUT + coG)) << 12);
#pragma unroll
        for (int nb = 0; nb < 8; ++nb) {
#pragma unroll
            for (int kT = 0; kT < 2; ++kT) {
                int q = co2*2 + kT;
                int T0 = Tbase + wn*64 + nb*8 + 2*t4 + kT;
                int rel = T0 & 1023;
                int tyy = rel >> 5, txx = rel & 31;
#pragma unroll
                for (int i = 0; i < 2; ++i) {
                    float2 v = make_float2(sc * Y[i*2 + 0][nb][q],
                                           sc * Y[i*2 + 1][nb][q]);
                    *(float2*)(ob + (2*tyy + i)*64 + 2*txx) = v;
                }
            }
        }
    }
}

// ================= launcher =================
extern "C" void kernel_launch(void* const* d_in, const int* in_sizes, int n_in,
                              void* d_out, int out_size) {
    const float* x = (const float*)d_in[0];   // [B, CIN, 64, 64]
    const float* s = (const float*)d_in[1];   // [B, CIN]
    const float* w = (const float*)d_in[2];   // [COUT, CIN, 3, 3]
    float* out = (float*)d_out;               // [B, COUT, 64, 64]

    cudaFuncSetAttribute(k_conv, cudaFuncAttributeMaxDynamicSharedMemorySize,
                         SMEM_BYTES);

    k_snorm<<<1, 256>>>(s);
    k_wstats<<<COUT, 256>>>(w);
    dim3 gs(COUT, B_);
    k_scale<<<gs, 256>>>(s);
    k_wino_w<<<COUT, 256>>>(w);
    dim3 gx(32, 8, B_);
    k_wino_x<<<gx, 256>>>(x, s);
    dim3 gc(4, 128);
    k_conv<<<gc, 256, SMEM_BYTES>>>(out);
}

// round 7
// speedup vs baseline: 1.2271x; 1.1204x over previous
#include <cuda_runtime.h>
#include <cuda_fp16.h>
#include <cstdint>

// Problem constants
#define B_    16
#define CIN   256
#define COUT  256
#define EPS_F 1e-8f
#define NT    16384            // Winograd tiles total (16 b * 32 * 32)

// ================= scratch =================
__device__ float g_snorm;
__device__ float g_wsq[COUT*CIN];
__device__ float g_invwn[COUT];
__device__ float g_scale[B_*COUT];
// V: [tap 16][T 16384][ci 256] fp16 (134MB)
__device__ __align__(16) __half g_V[(size_t)16*NT*CIN];
// U: [tap 16][co 256][ci 256] fp16 (2MB)
__device__ __align__(16) __half g_U[16*COUT*CIN];

// ================= helpers =================
__device__ __forceinline__ void mma_fp16(float& d0, float& d1, float& d2, float& d3,
                                         uint32_t a0, uint32_t a1, uint32_t a2, uint32_t a3,
                                         uint32_t b0, uint32_t b1) {
    asm volatile("mma.sync.aligned.m16n8k16.row.col.f32.f16.f16.f32 "
                 "{%0,%1,%2,%3}, {%4,%5,%6,%7}, {%8,%9}, {%0,%1,%2,%3};"
                 : "+f"(d0), "+f"(d1), "+f"(d2), "+f"(d3)
                 : "r"(a0), "r"(a1), "r"(a2), "r"(a3), "r"(b0), "r"(b1));
}
__device__ __forceinline__ void cp_async16(uint32_t saddr, const void* gaddr) {
    asm volatile("cp.async.cg.shared.global [%0], [%1], 16;"
                 :: "r"(saddr), "l"(gaddr) : "memory");
}
__device__ __forceinline__ void cp_commit() {
    asm volatile("cp.async.commit_group;" ::: "memory");
}
__device__ __forceinline__ void cp_wait2() {
    asm volatile("cp.async.wait_group 2;" ::: "memory");
}
__device__ __forceinline__ uint32_t smem_u32(const void* p) {
    uint32_t a;
    asm("{ .reg .u64 t; cvta.to.shared.u64 t, %1; cvt.u32.u64 %0, t; }"
        : "=r"(a) : "l"(p));
    return a;
}

// ================= norm/scale kernels (proven) =================
__global__ void k_snorm(const float* __restrict__ s) {
    __shared__ float red[256];
    float acc = 0.f;
    for (int i = threadIdx.x; i < B_*CIN; i += 256) { float v = s[i]; acc += v*v; }
    red[threadIdx.x] = acc; __syncthreads();
    for (int off = 128; off > 0; off >>= 1) {
        if (threadIdx.x < off) red[threadIdx.x] += red[threadIdx.x + off];
        __syncthreads();
    }
    if (threadIdx.x == 0) g_snorm = rsqrtf(red[0] / (float)(B_*CIN));
}
__global__ void k_wstats(const float* __restrict__ w) {
    __shared__ float red[256];
    int co = blockIdx.x, ci = threadIdx.x;
    const float* wp = w + ((size_t)co * CIN + ci) * 9;
    float s9 = 0.f;
#pragma unroll
    for (int k = 0; k < 9; k++) { float v = wp[k]; s9 += v*v; }
    g_wsq[co*CIN + ci] = s9;
    red[ci] = s9; __syncthreads();
    for (int off = 128; off > 0; off >>= 1) {
        if (ci < off) red[ci] += red[ci + off];
        __syncthreads();
    }
    if (ci == 0) g_invwn[co] = rsqrtf(red[0] / (float)(CIN*9));
}
__global__ void k_scale(const float* __restrict__ s) {
    __shared__ float red[256];
    int co = blockIdx.x, b = blockIdx.y, ci = threadIdx.x;
    float sn = s[b*CIN + ci] * g_snorm;
    red[ci] = sn*sn * g_wsq[co*CIN + ci]; __syncthreads();
    for (int off = 128; off > 0; off >>= 1) {
        if (ci < off) red[ci] += red[ci + off];
        __syncthreads();
    }
    if (ci == 0) {
        float iw = g_invwn[co];
        g_scale[b*COUT + co] = iw * rsqrtf(iw*iw*red[0] + EPS_F);
    }
}

// ================= weight transform: U = G g G^T =================
__global__ void k_wino_w(const float* __restrict__ w) {
    int co = blockIdx.x, ci = threadIdx.x;
    const float* gp = w + ((size_t)co*CIN + ci)*9;
    float g0[3], g1[3], g2[3];
#pragma unroll
    for (int c = 0; c < 3; ++c) { g0[c]=gp[c]; g1[c]=gp[3+c]; g2[c]=gp[6+c]; }
    float tm[4][3];
#pragma unroll
    for (int c = 0; c < 3; ++c) {
        tm[0][c] = g0[c];
        tm[1][c] = 0.5f*(g0[c] + g1[c] + g2[c]);
        tm[2][c] = 0.5f*(g0[c] - g1[c] + g2[c]);
        tm[3][c] = g2[c];
    }
#pragma unroll
    for (int r = 0; r < 4; ++r) {
        float u0 = tm[r][0];
        float u1 = 0.5f*(tm[r][0] + tm[r][1] + tm[r][2]);
        float u2 = 0.5f*(tm[r][0] - tm[r][1] + tm[r][2]);
        float u3 = tm[r][2];
        g_U[(((size_t)((r*4+0)*COUT + co))<<8) + ci] = __float2half_rn(u0);
        g_U[(((size_t)((r*4+1)*COUT + co))<<8) + ci] = __float2half_rn(u1);
        g_U[(((size_t)((r*4+2)*COUT + co))<<8) + ci] = __float2half_rn(u2);
        g_U[(((size_t)((r*4+3)*COUT + co))<<8) + ci] = __float2half_rn(u3);
    }
}

// ================= input transform: V = B^T (x*s*snorm) B =================
// grid (32 ty, 8 ciT, 16 b), 256 threads (= 32 ci x 8 txq, ci = lane)
__global__ void k_wino_x(const float* __restrict__ x, const float* __restrict__ s) {
    __shared__ float sm[4][32][67];
    const int tid = threadIdx.x;
    const int ty = blockIdx.x, ciT = blockIdx.y, b = blockIdx.z;
    const float snorm = g_snorm;
    const int r0 = 2*ty - 1;
#pragma unroll
    for (int k = 0; k < 8; ++k) {
        int lin = k*256 + tid;            // (ci 32)(r 4)(c4 16)
        int c4 = lin & 15, r = (lin >> 4) & 3, ci = lin >> 6;
        int gci = ciT*32 + ci;
        int gr = r0 + r;
        float4 v = make_float4(0.f, 0.f, 0.f, 0.f);
        if ((unsigned)gr < 64u)
            v = *(const float4*)(x + (((size_t)(b*CIN + gci)) << 12) + gr*64 + c4*4);
        float m = s[b*CIN + gci] * snorm;
        float* d = &sm[r][ci][1 + 4*c4];
        d[0] = v.x*m; d[1] = v.y*m; d[2] = v.z*m; d[3] = v.w*m;
        if (c4 == 0)  sm[r][ci][0]  = 0.f;
        if (c4 == 15) sm[r][ci][65] = 0.f;
    }
    __syncthreads();
    const int ci = tid & 31, txq = tid >> 5;
#pragma unroll
    for (int k = 0; k < 4; ++k) {
        int tx = txq + 8*k;
        float d[4][4];
#pragma unroll
        for (int r = 0; r < 4; ++r)
#pragma unroll
            for (int c = 0; c < 4; ++c) d[r][c] = sm[r][ci][2*tx + c];
        float m0[4], m1[4], m2[4], m3[4];
#pragma unroll
        for (int j = 0; j < 4; ++j) {
            m0[j] = d[0][j] - d[2][j];
            m1[j] = d[1][j] + d[2][j];
            m2[j] = d[2][j] - d[1][j];
            m3[j] = d[1][j] - d[3][j];
        }
        float V[4][4];
#pragma unroll
        for (int r = 0; r < 4; ++r) {
            const float* mr = (r==0)?m0:(r==1)?m1:(r==2)?m2:m3;
            V[r][0] = mr[0] - mr[2];
            V[r][1] = mr[1] + mr[2];
            V[r][2] = mr[2] - mr[1];
            V[r][3] = mr[1] - mr[3];
        }
        int T = b*1024 + ty*32 + tx;
#pragma unroll
        for (int r = 0; r < 4; ++r)
#pragma unroll
            for (int c = 0; c < 4; ++c)
                g_V[(((size_t)((r*4+c)*NT + T)) << 8) + ciT*32 + ci] =
                    __float2half_rn(V[r][c]);
    }
}

// ================= Winograd GEMM + fused inverse transform =================
// CTA: 64 co x 64 T. 8 warps: wm = wid&3 (m16), wn = wid>>2 (n32).
// 64 phases = 16 taps x 4 ci-chunks(64). 4-stage cp.async pipeline,
// wait_group 2 BEFORE compute, one barrier/phase, 2 CTAs/SM.
#define ASTR 72
#define A_HALFS (64*ASTR)
#define B_HALFS (64*ASTR)
#define STAGE_HALFS (A_HALFS + B_HALFS)          // 9216
#define NSTAGE 4
#define SMEM_BYTES (NSTAGE*STAGE_HALFS*2)        // 73728

__global__ __launch_bounds__(256, 2)
void k_conv(float* __restrict__ out) {
    extern __shared__ __half smem[];
    const uint32_t smem_base = smem_u32(smem);

    const int t    = threadIdx.x;
    const int lane = t & 31;
    const int wm   = (t >> 5) & 3;        // co block (m16)
    const int wn   = t >> 7;              // T block (n32)
    const int g    = lane >> 2;
    const int t4   = lane & 3;

    const int coT   = blockIdx.x;         // 0..3 (fastest: B-slab L2 reuse)
    const int Tbase = blockIdx.y * 64;    // 0..16320
    const int b     = Tbase >> 10;

    float Y[4][4][4];
#pragma unroll
    for (int px = 0; px < 4; ++px)
#pragma unroll
        for (int nb = 0; nb < 4; ++nb)
#pragma unroll
            for (int q = 0; q < 4; ++q) Y[px][nb][q] = 0.f;

    // ---- phase loader (tap = p>>2, kc = p&3) into stage j ----
    auto load_phase = [&](int p, int j) {
        int tap = p >> 2, kc = p & 3;
        uint32_t sbase = smem_base + (j*STAGE_HALFS)*2;
        // A: 512 uint4 (64 co rows x 8 q), 2/thread
#pragma unroll
        for (int k2 = 0; k2 < 2; ++k2) {
            int lin = k2*256 + t;
            int row = lin >> 3, q = lin & 7;
            const __half* src = g_U + (((size_t)(tap*COUT + coT*64 + row)) << 8)
                              + kc*64 + q*8;
            cp_async16(sbase + (row*ASTR + q*8)*2, src);
        }
        // B: 512 uint4 (64 T rows x 8 q), 2/thread
#pragma unroll
        for (int k2 = 0; k2 < 2; ++k2) {
            int lin = k2*256 + t;
            int row = lin >> 3, q = lin & 7;
            const __half* src = g_V + (((size_t)(tap*NT + Tbase + row)) << 8)
                              + kc*64 + q*8;
            cp_async16(sbase + (A_HALFS + row*ASTR + q*8)*2, src);
        }
    };

    // prologue: stages 0..2
#pragma unroll
    for (int p = 0; p < 3; ++p) { load_phase(p, p); cp_commit(); }

    float M[4][4];
    const int AT0[4] = {1, 1, 1, 0};
    const int AT1[4] = {0, 1, -1, -1};

    for (int p = 0; p < 64; ++p) {
        const int j = p & 3;
        cp_wait2();             // stage j resident; p+1, p+2 in flight
        __syncthreads();        // slot (p-1)&3 reusable after this
        if (p + 3 < 64) load_phase(p + 3, (p + 3) & 3);
        cp_commit();            // invariant group count

        if ((p & 3) == 0) {
#pragma unroll
            for (int nb = 0; nb < 4; ++nb)
#pragma unroll
                for (int q = 0; q < 4; ++q) M[nb][q] = 0.f;
        }

        const __half* A  = smem + j*STAGE_HALFS;
        const __half* Bm = A + A_HALFS;
#pragma unroll
        for (int ks = 0; ks < 4; ++ks) {
            const __half* ap = A + (wm*16 + g)*ASTR + ks*16 + 2*t4;
            uint32_t a0 = *(const uint32_t*)(ap);
            uint32_t a1 = *(const uint32_t*)(ap + 8*ASTR);
            uint32_t a2 = *(const uint32_t*)(ap + 8);
            uint32_t a3 = *(const uint32_t*)(ap + 8*ASTR + 8);
            uint32_t bf[4][2];
#pragma unroll
            for (int nb = 0; nb < 4; ++nb) {
                const __half* bp = Bm + (wn*32 + nb*8 + g)*ASTR + ks*16 + 2*t4;
                bf[nb][0] = *(const uint32_t*)(bp);
                bf[nb][1] = *(const uint32_t*)(bp + 8);
            }
#pragma unroll
            for (int nb = 0; nb < 4; ++nb)
                mma_fp16(M[nb][0], M[nb][1], M[nb][2], M[nb][3],
                         a0, a1, a2, a3, bf[nb][0], bf[nb][1]);
        }

        if ((p & 3) == 3) {
            int tap = p >> 2;
            int r = tap >> 2, c = tap & 3;
#pragma unroll
            for (int i = 0; i < 2; ++i) {
                int ar = (i == 0) ? AT0[r] : AT1[r];
                if (ar == 0) continue;
#pragma unroll
                for (int jj = 0; jj < 2; ++jj) {
                    int ac = (jj == 0) ? AT0[c] : AT1[c];
                    if (ac == 0) continue;
                    float cf = (float)(ar * ac);
#pragma unroll
                    for (int nb = 0; nb < 4; ++nb)
#pragma unroll
                        for (int q = 0; q < 4; ++q)
                            Y[i*2 + jj][nb][q] += cf * M[nb][q];
                }
            }
        }
    }

    // ---- epilogue: demod scale + scatter 2x2 px per tile ----
#pragma unroll
    for (int co2 = 0; co2 < 2; ++co2) {
        int coG = coT*64 + wm*16 + g + co2*8;
        float sc = g_scale[b*COUT + coG];
        float* ob = out + (((size_t)(b*COUT + coG)) << 12);
#pragma unroll
        for (int nb = 0; nb < 4; ++nb) {
#pragma unroll
            for (int kT = 0; kT < 2; ++kT) {
                int q = co2*2 + kT;
                int T0 = Tbase + wn*32 + nb*8 + 2*t4 + kT;
                int rel = T0 & 1023;
                int tyy = rel >> 5, txx = rel & 31;
#pragma unroll
                for (int i = 0; i < 2; ++i) {
                    float2 v = make_float2(sc * Y[i*2 + 0][nb][q],
                                           sc * Y[i*2 + 1][nb][q]);
                    *(float2*)(ob + (2*tyy + i)*64 + 2*txx) = v;
                }
            }
        }
    }
}

// ================= launcher =================
extern "C" void kernel_launch(void* const* d_in, const int* in_sizes, int n_in,
                              void* d_out, int out_size) {
    const float* x = (const float*)d_in[0];   // [B, CIN, 64, 64]
    const float* s = (const float*)d_in[1];   // [B, CIN]
    const float* w = (const float*)d_in[2];   // [COUT, CIN, 3, 3]
    float* out = (float*)d_out;               // [B, COUT, 64, 64]

    cudaFuncSetAttribute(k_conv, cudaFuncAttributeMaxDynamicSharedMemorySize,
                         SMEM_BYTES);

    k_snorm<<<1, 256>>>(s);
    k_wstats<<<COUT, 256>>>(w);
    dim3 gs(COUT, B_);
    k_scale<<<gs, 256>>>(s);
    k_wino_w<<<COUT, 256>>>(w);
    dim3 gx(32, 8, B_);
    k_wino_x<<<gx, 256>>>(x, s);
    dim3 gc(4, 256);
    k_conv<<<gc, 256, SMEM_BYTES>>>(out);
}

// round 9
// speedup vs baseline: 1.3126x; 1.0697x over previous
#include <cuda_runtime.h>
#include <cuda_fp16.h>
#include <cstdint>

// Problem constants
#define B_    16
#define CIN   256
#define COUT  256
#define EPS_F 1e-8f
#define NT    16384            // Winograd tiles total (16 b * 32 * 32)

// ================= scratch =================
__device__ float g_snorm;
__device__ float g_wsq[COUT*CIN];
__device__ float g_invwn[COUT];
__device__ float g_scale[B_*COUT];
// V: [tap 16][T 16384][ci 256] fp16 (134MB)
__device__ __align__(16) __half g_V[(size_t)16*NT*CIN];
// U: [tap 16][co 256][ci 256] fp16 (2MB)
__device__ __align__(16) __half g_U[16*COUT*CIN];
// M: [tap 16][co 256][T 16384] fp16 (134MB)
__device__ __align__(16) __half g_M[(size_t)16*COUT*NT];

// ================= helpers =================
__device__ __forceinline__ void mma_fp16(float& d0, float& d1, float& d2, float& d3,
                                         uint32_t a0, uint32_t a1, uint32_t a2, uint32_t a3,
                                         uint32_t b0, uint32_t b1) {
    asm volatile("mma.sync.aligned.m16n8k16.row.col.f32.f16.f16.f32 "
                 "{%0,%1,%2,%3}, {%4,%5,%6,%7}, {%8,%9}, {%0,%1,%2,%3};"
                 : "+f"(d0), "+f"(d1), "+f"(d2), "+f"(d3)
                 : "r"(a0), "r"(a1), "r"(a2), "r"(a3), "r"(b0), "r"(b1));
}
__device__ __forceinline__ void cp_async16(uint32_t saddr, const void* gaddr) {
    asm volatile("cp.async.cg.shared.global [%0], [%1], 16;"
                 :: "r"(saddr), "l"(gaddr) : "memory");
}
__device__ __forceinline__ void cp_commit() {
    asm volatile("cp.async.commit_group;" ::: "memory");
}
__device__ __forceinline__ void cp_wait2() {
    asm volatile("cp.async.wait_group 2;" ::: "memory");
}
__device__ __forceinline__ uint32_t smem_u32(const void* p) {
    uint32_t a;
    asm("{ .reg .u64 t; cvta.to.shared.u64 t, %1; cvt.u32.u64 %0, t; }"
        : "=r"(a) : "l"(p));
    return a;
}

// ================= norm/scale kernels (proven) =================
__global__ void k_snorm(const float* __restrict__ s) {
    __shared__ float red[256];
    float acc = 0.f;
    for (int i = threadIdx.x; i < B_*CIN; i += 256) { float v = s[i]; acc += v*v; }
    red[threadIdx.x] = acc; __syncthreads();
    for (int off = 128; off > 0; off >>= 1) {
        if (threadIdx.x < off) red[threadIdx.x] += red[threadIdx.x + off];
        __syncthreads();
    }
    if (threadIdx.x == 0) g_snorm = rsqrtf(red[0] / (float)(B_*CIN));
}
__global__ void k_wstats(const float* __restrict__ w) {
    __shared__ float red[256];
    int co = blockIdx.x, ci = threadIdx.x;
    const float* wp = w + ((size_t)co * CIN + ci) * 9;
    float s9 = 0.f;
#pragma unroll
    for (int k = 0; k < 9; k++) { float v = wp[k]; s9 += v*v; }
    g_wsq[co*CIN + ci] = s9;
    red[ci] = s9; __syncthreads();
    for (int off = 128; off > 0; off >>= 1) {
        if (ci < off) red[ci] += red[ci + off];
        __syncthreads();
    }
    if (ci == 0) g_invwn[co] = rsqrtf(red[0] / (float)(CIN*9));
}
__global__ void k_scale(const float* __restrict__ s) {
    __shared__ float red[256];
    int co = blockIdx.x, b = blockIdx.y, ci = threadIdx.x;
    float sn = s[b*CIN + ci] * g_snorm;
    red[ci] = sn*sn * g_wsq[co*CIN + ci]; __syncthreads();
    for (int off = 128; off > 0; off >>= 1) {
        if (ci < off) red[ci] += red[ci + off];
        __syncthreads();
    }
    if (ci == 0) {
        float iw = g_invwn[co];
        g_scale[b*COUT + co] = iw * rsqrtf(iw*iw*red[0] + EPS_F);
    }
}

// ================= weight transform: U = G g G^T =================
__global__ void k_wino_w(const float* __restrict__ w) {
    int co = blockIdx.x, ci = threadIdx.x;
    const float* gp = w + ((size_t)co*CIN + ci)*9;
    float g0[3], g1[3], g2[3];
#pragma unroll
    for (int c = 0; c < 3; ++c) { g0[c]=gp[c]; g1[c]=gp[3+c]; g2[c]=gp[6+c]; }
    float tm[4][3];
#pragma unroll
    for (int c = 0; c < 3; ++c) {
        tm[0][c] = g0[c];
        tm[1][c] = 0.5f*(g0[c] + g1[c] + g2[c]);
        tm[2][c] = 0.5f*(g0[c] - g1[c] + g2[c]);
        tm[3][c] = g2[c];
    }
#pragma unroll
    for (int r = 0; r < 4; ++r) {
        float u0 = tm[r][0];
        float u1 = 0.5f*(tm[r][0] + tm[r][1] + tm[r][2]);
        float u2 = 0.5f*(tm[r][0] - tm[r][1] + tm[r][2]);
        float u3 = tm[r][2];
        g_U[(((size_t)((r*4+0)*COUT + co))<<8) + ci] = __float2half_rn(u0);
        g_U[(((size_t)((r*4+1)*COUT + co))<<8) + ci] = __float2half_rn(u1);
        g_U[(((size_t)((r*4+2)*COUT + co))<<8) + ci] = __float2half_rn(u2);
        g_U[(((size_t)((r*4+3)*COUT + co))<<8) + ci] = __float2half_rn(u3);
    }
}

// ================= input transform: V = B^T (x*s*snorm) B =================
__global__ void k_wino_x(const float* __restrict__ x, const float* __restrict__ s) {
    __shared__ float sm[4][32][67];
    const int tid = threadIdx.x;
    const int ty = blockIdx.x, ciT = blockIdx.y, b = blockIdx.z;
    const float snorm = g_snorm;
    const int r0 = 2*ty - 1;
#pragma unroll
    for (int k = 0; k < 8; ++k) {
        int lin = k*256 + tid;            // (ci 32)(r 4)(c4 16)
        int c4 = lin & 15, r = (lin >> 4) & 3, ci = lin >> 6;
        int gci = ciT*32 + ci;
        int gr = r0 + r;
        float4 v = make_float4(0.f, 0.f, 0.f, 0.f);
        if ((unsigned)gr < 64u)
            v = *(const float4*)(x + (((size_t)(b*CIN + gci)) << 12) + gr*64 + c4*4);
        float m = s[b*CIN + gci] * snorm;
        float* d = &sm[r][ci][1 + 4*c4];
        d[0] = v.x*m; d[1] = v.y*m; d[2] = v.z*m; d[3] = v.w*m;
        if (c4 == 0)  sm[r][ci][0]  = 0.f;
        if (c4 == 15) sm[r][ci][65] = 0.f;
    }
    __syncthreads();
    const int ci = tid & 31, txq = tid >> 5;
#pragma unroll
    for (int k = 0; k < 4; ++k) {
        int tx = txq + 8*k;
        float d[4][4];
#pragma unroll
        for (int r = 0; r < 4; ++r)
#pragma unroll
            for (int c = 0; c < 4; ++c) d[r][c] = sm[r][ci][2*tx + c];
        float m0[4], m1[4], m2[4], m3[4];
#pragma unroll
        for (int j = 0; j < 4; ++j) {
            m0[j] = d[0][j] - d[2][j];
            m1[j] = d[1][j] + d[2][j];
            m2[j] = d[2][j] - d[1][j];
            m3[j] = d[1][j] - d[3][j];
        }
        float V[4][4];
#pragma unroll
        for (int r = 0; r < 4; ++r) {
            const float* mr = (r==0)?m0:(r==1)?m1:(r==2)?m2:m3;
            V[r][0] = mr[0] - mr[2];
            V[r][1] = mr[1] + mr[2];
            V[r][2] = mr[2] - mr[1];
            V[r][3] = mr[1] - mr[3];
        }
        int T = b*1024 + ty*32 + tx;
#pragma unroll
        for (int r = 0; r < 4; ++r)
#pragma unroll
            for (int c = 0; c < 4; ++c)
                g_V[(((size_t)((r*4+c)*NT + T)) << 8) + ciT*32 + ci] =
                    __float2half_rn(V[r][c]);
    }
}

// ================= kernel A: batched GEMM  M[tap] = U[tap] x V[tap] ====
// CTA 128co x 128T, warp m32 x n64 (8 warps: wm=wid&3, wn=wid>>2).
// K=256 in 8 phases of 32. 4-stage cp.async, one barrier/phase, 2 CTA/SM.
#define KSTR 40
#define AT_HALFS (128*KSTR)                      // 5120
#define STG_HALFS (2*AT_HALFS)                   // 10240
#define GSMEM_BYTES (4*STG_HALFS*2)              // 81920
#define MSTR 136

__global__ __launch_bounds__(256, 2)
void k_gemm() {
    extern __shared__ __half smem[];
    const uint32_t smem_base = smem_u32(smem);

    const int t    = threadIdx.x;
    const int lane = t & 31;
    const int wm   = (t >> 5) & 3;        // m32 block
    const int wn   = t >> 7;              // n64 block
    const int g    = lane >> 2;
    const int t4   = lane & 3;

    const int coT   = blockIdx.x;         // 0..1 (fastest: shares V slab in L2)
    const int Tbase = blockIdx.y * 128;
    const int tap   = blockIdx.z;

    float c[2][8][4];
#pragma unroll
    for (int mb = 0; mb < 2; ++mb)
#pragma unroll
        for (int nb = 0; nb < 8; ++nb)
#pragma unroll
            for (int q = 0; q < 4; ++q) c[mb][nb][q] = 0.f;

    auto load_phase = [&](int p, int j) {
        uint32_t sbase = smem_base + (j*STG_HALFS)*2;
        // A: 128 co-rows x 32 halves = 512 uint4, 2/thread
#pragma unroll
        for (int k2 = 0; k2 < 2; ++k2) {
            int lin = k2*256 + t;
            int row = lin >> 2, q = lin & 3;
            const __half* src = g_U + (((size_t)(tap*COUT + coT*128 + row)) << 8)
                              + p*32 + q*8;
            cp_async16(sbase + (row*KSTR + q*8)*2, src);
        }
        // B: 128 T-rows x 32 halves = 512 uint4, 2/thread
#pragma unroll
        for (int k2 = 0; k2 < 2; ++k2) {
            int lin = k2*256 + t;
            int row = lin >> 2, q = lin & 3;
            const __half* src = g_V + (((size_t)(tap*NT + Tbase + row)) << 8)
                              + p*32 + q*8;
            cp_async16(sbase + (AT_HALFS + row*KSTR + q*8)*2, src);
        }
    };

#pragma unroll
    for (int p = 0; p < 3; ++p) { load_phase(p, p); cp_commit(); }

    for (int p = 0; p < 8; ++p) {
        const int j = p & 3;
        cp_wait2();
        __syncthreads();
        if (p + 3 < 8) load_phase(p + 3, (p + 3) & 3);
        cp_commit();

        const __half* A  = smem + j*STG_HALFS;
        const __half* Bm = A + AT_HALFS;
#pragma unroll
        for (int ks = 0; ks < 2; ++ks) {
            uint32_t a[2][4];
#pragma unroll
            for (int mb = 0; mb < 2; ++mb) {
                const __half* ap = A + (wm*32 + mb*16 + g)*KSTR + ks*16 + 2*t4;
                a[mb][0] = *(const uint32_t*)(ap);
                a[mb][1] = *(const uint32_t*)(ap + 8*KSTR);
                a[mb][2] = *(const uint32_t*)(ap + 8);
                a[mb][3] = *(const uint32_t*)(ap + 8*KSTR + 8);
            }
            uint32_t bf[8][2];
#pragma unroll
            for (int nb = 0; nb < 8; ++nb) {
                const __half* bp = Bm + (wn*64 + nb*8 + g)*KSTR + ks*16 + 2*t4;
                bf[nb][0] = *(const uint32_t*)(bp);
                bf[nb][1] = *(const uint32_t*)(bp + 8);
            }
#pragma unroll
            for (int mb = 0; mb < 2; ++mb)
#pragma unroll
                for (int nb = 0; nb < 8; ++nb)
                    mma_fp16(c[mb][nb][0], c[mb][nb][1], c[mb][nb][2], c[mb][nb][3],
                             a[mb][0], a[mb][1], a[mb][2], a[mb][3],
                             bf[nb][0], bf[nb][1]);
        }
    }
    __syncthreads();   // all compute done; smem reusable for M staging

    // ---- epilogue: stage fp16 M tile in smem, then coalesced store ----
    __half* sM = smem;   // [128 co][MSTR]
#pragma unroll
    for (int mb = 0; mb < 2; ++mb) {
        int r0 = wm*32 + mb*16 + g;
        int col = wn*64 + 2*t4;
#pragma unroll
        for (int nb = 0; nb < 8; ++nb) {
            __half2 h01 = __floats2half2_rn(c[mb][nb][0], c[mb][nb][1]);
            __half2 h23 = __floats2half2_rn(c[mb][nb][2], c[mb][nb][3]);
            *(__half2*)(sM + r0*MSTR + col + nb*8) = h01;
            *(__half2*)(sM + (r0+8)*MSTR + col + nb*8) = h23;
        }
    }
    __syncthreads();
    // full tile = 128 rows x 16 uint4 = 2048 uint4 -> 8 passes of 256 thr
#pragma unroll
    for (int it = 0; it < 8; ++it) {
        int lin = it*256 + t;
        int row = lin >> 4, q = lin & 15;
        uint4 v = *(const uint4*)(sM + row*MSTR + q*8);
        *(uint4*)(g_M + ((size_t)(tap*COUT + coT*128 + row))*NT
                        + Tbase + q*8) = v;
    }
}

// ================= kernel B: inverse transform + demod scale ==========
// grid (32 ty, 32 coG, 16 b), 256 thr (8 warps); warp -> one co; lane -> tx
__global__ __launch_bounds__(256)
void k_inv(float* __restrict__ out) {
    const int lane = threadIdx.x & 31;
    const int wid  = threadIdx.x >> 5;
    const int ty   = blockIdx.x;
    const int co   = blockIdx.y*8 + wid;
    const int b    = blockIdx.z;
    const int T    = b*1024 + ty*32 + lane;

    float m[16];
#pragma unroll
    for (int tap = 0; tap < 16; ++tap)
        m[tap] = __half2float(g_M[((size_t)(tap*COUT + co))*NT + T]);

    float t0[4], t1[4];
#pragma unroll
    for (int cc = 0; cc < 4; ++cc) {
        t0[cc] = m[cc] + m[4+cc] + m[8+cc];
        t1[cc] = m[4+cc] - m[8+cc] - m[12+cc];
    }
    float y00 = t0[0] + t0[1] + t0[2];
    float y01 = t0[1] - t0[2] - t0[3];
    float y10 = t1[0] + t1[1] + t1[2];
    float y11 = t1[1] - t1[2] - t1[3];

    float sc = g_scale[b*COUT + co];
    float* ob = out + (((size_t)(b*COUT + co)) << 12) + (2*ty)*64 + 2*lane;
    *(float2*)(ob)      = make_float2(sc*y00, sc*y01);
    *(float2*)(ob + 64) = make_float2(sc*y10, sc*y11);
}

// ================= launcher =================
extern "C" void kernel_launch(void* const* d_in, const int* in_sizes, int n_in,
                              void* d_out, int out_size) {
    const float* x = (const float*)d_in[0];   // [B, CIN, 64, 64]
    const float* s = (const float*)d_in[1];   // [B, CIN]
    const float* w = (const float*)d_in[2];   // [COUT, CIN, 3, 3]
    float* out = (float*)d_out;               // [B, COUT, 64, 64]

    cudaFuncSetAttribute(k_gemm, cudaFuncAttributeMaxDynamicSharedMemorySize,
                         GSMEM_BYTES);

    k_snorm<<<1, 256>>>(s);
    k_wstats<<<COUT, 256>>>(w);
    dim3 gs(COUT, B_);
    k_scale<<<gs, 256>>>(s);
    k_wino_w<<<COUT, 256>>>(w);
    dim3 gx(32, 8, B_);
    k_wino_x<<<gx, 256>>>(x, s);
    dim3 gg(2, 128, 16);
    k_gemm<<<gg, 256, GSMEM_BYTES>>>();
    dim3 gi(32, 32, B_);
    k_inv<<<gi, 256>>>(out);
}